// round 1
// baseline (speedup 1.0000x reference)
#include <cuda_runtime.h>

// Problem constants
#define NG   40      // groups
#define CPG  8       // channels per group (320/40)
#define ND   48      // disparity bins
#define NH   128
#define NW   240
#define NCC  12      // concat channels per tensor
#define PAD  48      // left zero-pad for shifted tgt (>= max d)
#define TROW (NW + PAD)   // 288 floats per padded tgt row

// ---------------------------------------------------------------------------
// Kernel 1: groupwise-correlation volume, channels [0, 40) of the output.
// Block = (group g, row h). Smem holds ref row tile [8][240] and zero-padded
// tgt row tile [8][288]. Each thread owns a 4w x 4d register tile and loops
// over 3 d-quads; ref stays in registers, tgt window comes from 2 aligned
// LDS.128 per channel (16 B smem traffic / output).
// ---------------------------------------------------------------------------
__global__ __launch_bounds__(256) void gwc_kernel(const float* __restrict__ ref,
                                                  const float* __restrict__ tgt,
                                                  float* __restrict__ out) {
    __shared__ __align__(16) float sref[CPG * NW];    // 1920 floats
    __shared__ __align__(16) float stgt[CPG * TROW];  // 2304 floats

    const int g   = blockIdx.x;   // 0..39
    const int h   = blockIdx.y;   // 0..127
    const int tid = threadIdx.x;

    const float* gref = ref + ((size_t)(g * CPG) * NH + h) * NW;
    const float* gtgt = tgt + ((size_t)(g * CPG) * NH + h) * NW;

    // Cooperative loads (all float4, coalesced)
    for (int i = tid; i < CPG * (NW / 4); i += 256) {         // ref rows
        int c = i / (NW / 4), wq = i % (NW / 4);
        float4 v = *(const float4*)(gref + (size_t)c * NH * NW + wq * 4);
        *(float4*)(sref + c * NW + wq * 4) = v;
    }
    for (int i = tid; i < CPG * (PAD / 4); i += 256) {        // zero pad
        int c = i / (PAD / 4), pq = i % (PAD / 4);
        *(float4*)(stgt + c * TROW + pq * 4) = make_float4(0.f, 0.f, 0.f, 0.f);
    }
    for (int i = tid; i < CPG * (NW / 4); i += 256) {         // tgt rows
        int c = i / (NW / 4), wq = i % (NW / 4);
        float4 v = *(const float4*)(gtgt + (size_t)c * NH * NW + wq * 4);
        *(float4*)(stgt + c * TROW + PAD + wq * 4) = v;
    }
    __syncthreads();

    const int wq   = tid & 63;   // w-quad: 0..59 active
    const int dgrp = tid >> 6;   // 0..3
    if (wq >= NW / 4) return;
    const int w0 = wq * 4;

    // ref[c][w0..w0+3] held in registers across all d
    float r[CPG][4];
#pragma unroll
    for (int c = 0; c < CPG; c++) {
        float4 v = *(const float4*)(sref + c * NW + w0);
        r[c][0] = v.x; r[c][1] = v.y; r[c][2] = v.z; r[c][3] = v.w;
    }

    float* outbase = out + (size_t)g * ND * (NH * NW) + (size_t)h * NW + w0;

#pragma unroll
    for (int k = 0; k < 3; k++) {
        const int d0 = (dgrp + 4 * k) * 4;   // d-quad base: covers all 12 quads
        float acc[4][4] = {};                // [j=d][i=w]
#pragma unroll
        for (int c = 0; c < CPG; c++) {
            // window tgt[w0-d0-4 .. w0-d0+3] (aligned: w0-d0 ≡ 0 mod 4)
            const float* tp = stgt + c * TROW + PAD + w0 - d0 - 4;
            float4 lo = *(const float4*)tp;
            float4 hi = *(const float4*)(tp + 4);
            float v[8] = {lo.x, lo.y, lo.z, lo.w, hi.x, hi.y, hi.z, hi.w};
#pragma unroll
            for (int j = 0; j < 4; j++)
#pragma unroll
                for (int i = 0; i < 4; i++)
                    acc[j][i] += r[c][i] * v[4 + i - j];  // tgt[w0+i-(d0+j)]
        }
#pragma unroll
        for (int j = 0; j < 4; j++) {
            float4 o;
            o.x = acc[j][0] * 0.125f;
            o.y = acc[j][1] * 0.125f;
            o.z = acc[j][2] * 0.125f;
            o.w = acc[j][3] * 0.125f;
            *(float4*)(outbase + (size_t)(d0 + j) * (NH * NW)) = o;
        }
    }
}

// ---------------------------------------------------------------------------
// Kernel 2: concat volume, channels [40, 64) of the output.
// Pure replication + shift. Inputs (1.47 MB each) fully live in L2;
// one thread per output float4.
// ---------------------------------------------------------------------------
__global__ __launch_bounds__(256) void concat_kernel(const float* __restrict__ refc,
                                                     const float* __restrict__ tgtc,
                                                     float* __restrict__ out) {
    const int NQ = 2 * NCC * ND * NH * (NW / 4);   // 8,847,360 float4s
    int idx = blockIdx.x * 256 + threadIdx.x;
    if (idx >= NQ) return;

    int wq = idx % (NW / 4);
    int t  = idx / (NW / 4);
    int h  = t % NH;  t /= NH;
    int d  = t % ND;
    int c  = t / ND;          // 0..23
    const int w0 = wq * 4;

    float o[4];
    if (c < NCC) {
        // ref_concat masked by (w >= d)
        const float* p = refc + ((size_t)c * NH + h) * NW + w0;
#pragma unroll
        for (int i = 0; i < 4; i++)
            o[i] = (w0 + i >= d) ? p[i] : 0.f;
    } else {
        // tgt_concat shifted right by d (zero-fill left)
        const float* p = tgtc + ((size_t)(c - NCC) * NH + h) * NW;
#pragma unroll
        for (int i = 0; i < 4; i++) {
            int wi = w0 + i - d;
            int wi_c = wi < 0 ? 0 : wi;          // clamp so the load is in-bounds
            float val = p[wi_c];
            o[i] = (wi >= 0) ? val : 0.f;
        }
    }

    float4 v = make_float4(o[0], o[1], o[2], o[3]);
    *(float4*)(out + ((size_t)(NG + c) * ND + d) * (NH * NW) + (size_t)h * NW + w0) = v;
}

// ---------------------------------------------------------------------------
extern "C" void kernel_launch(void* const* d_in, const int* in_sizes, int n_in,
                              void* d_out, int out_size) {
    (void)in_sizes; (void)n_in; (void)out_size;
    const float* ref_gwc = (const float*)d_in[0];
    const float* tgt_gwc = (const float*)d_in[1];
    const float* ref_c   = (const float*)d_in[2];
    const float* tgt_c   = (const float*)d_in[3];
    float* out = (float*)d_out;

    gwc_kernel<<<dim3(NG, NH), 256>>>(ref_gwc, tgt_gwc, out);

    const int NQ = 2 * NCC * ND * NH * (NW / 4);
    concat_kernel<<<(NQ + 255) / 256, 256>>>(ref_c, tgt_c, out);
}